// round 12
// baseline (speedup 1.0000x reference)
#include <cuda_runtime.h>
#include <cuda_bf16.h>

// Problem constants
#define S 8192
#define D 1024
#define E 64
#define CAP 128
#define SHIFT 4096
static const long long SEC = (long long)S * E * CAP;   // 67108864

#define GEMM_BLOCKS 256              // BM=32
#define ZERO_BLOCKS 1280
#define BM 32

// ---------------- scratch (device globals) ----------------------------------
__device__ int   g_beste[S];
__device__ float g_gmax[S];
__device__ int   g_expert_at_p[S];
__device__ int   g_token_at_p[S];
__device__ int   g_hist[S];          // [128 chunks][64 experts]; zeroed in k1
__device__ int   g_choff[S];
__device__ float g_me_part[GEMM_BLOCKS * E];
__device__ int   g_cnt_part[GEMM_BLOCKS * E];
__device__ unsigned g_done, g_c4;    // k3 flag + reset counter (self-reset)

// ---------------------------------------------------------------------------
// K1: blocks 0..255 : GEMM (32 tokens x 64 experts) + softmax epilogue
//     blocks 256..  : grid-stride zero-fill, high occupancy (6 blocks/SM)
// ---------------------------------------------------------------------------
__global__ void __launch_bounds__(256, 6)
k1_fused(const float* __restrict__ x, const float* __restrict__ w,
         float* __restrict__ out, long long out_size) {
    const int tid = threadIdx.x;

    if (blockIdx.x >= GEMM_BLOCKS) {
        // ---- zero-fill the whole output buffer (poisoned to 0xAA) ----
        long long n4 = out_size >> 2;
        float4* o4 = (float4*)out;
        const float4 z = make_float4(0.f, 0.f, 0.f, 0.f);
        long long idx    = (long long)(blockIdx.x - GEMM_BLOCKS) * 256 + tid;
        const long long stride = (long long)ZERO_BLOCKS * 256;
        #pragma unroll 4
        for (; idx < n4; idx += stride) o4[idx] = z;
        if (blockIdx.x == GEMM_BLOCKS) {
            for (long long i = (n4 << 2) + tid; i < out_size; i += 256)
                out[i] = 0.0f;
            for (int i = tid; i < S; i += 256) g_hist[i] = 0;  // pre-zero hist
        }
        return;
    }

    // ---- GEMM: BM=32, BN=64, BK=32, 256 thr, 2x4 micro-tile (~40 regs) ----
    __shared__ float As[32][BM];     // [k][m]  1024 f
    __shared__ float Bs[32][64];     // [k][e]  2048 f
    __shared__ float L[BM][65];
    __shared__ float smax[BM], sinv[BM];
    __shared__ int   scnt[E];

    const int m0 = blockIdx.x * BM;
    const int tx = tid & 15;         // expert group (4 experts)
    const int ty = tid >> 4;         // row group (2 rows)
    float acc[2][4];
    #pragma unroll
    for (int i = 0; i < 2; i++)
        #pragma unroll
        for (int j = 0; j < 4; j++) acc[i][j] = 0.0f;

    for (int k0 = 0; k0 < D; k0 += 32) {
        #pragma unroll
        for (int r = 0; r < 4; r++) {
            int l  = tid + r * 256;
            int mm = l & 31;
            int kk = l >> 5;
            As[kk][mm] = x[(long long)(m0 + mm) * D + k0 + kk];
        }
        #pragma unroll
        for (int r = 0; r < 8; r++) {
            int l  = tid + r * 256;
            int mm = l & 63;
            int kk = l >> 6;
            Bs[kk][mm] = w[(long long)mm * D + k0 + kk];
        }
        __syncthreads();
        #pragma unroll
        for (int kk = 0; kk < 32; kk++) {
            const float2 a = *(const float2*)(&As[kk][ty * 2]);
            const float4 b = *(const float4*)(&Bs[kk][tx * 4]);
            float av[2] = {a.x, a.y};
            float bv[4] = {b.x, b.y, b.z, b.w};
            #pragma unroll
            for (int i = 0; i < 2; i++)
                #pragma unroll
                for (int j = 0; j < 4; j++)
                    acc[i][j] += av[i] * bv[j];
        }
        __syncthreads();
    }

    #pragma unroll
    for (int i = 0; i < 2; i++)
        #pragma unroll
        for (int j = 0; j < 4; j++)
            L[ty * 2 + i][tx * 4 + j] = acc[i][j];
    if (tid < E) scnt[tid] = 0;
    __syncthreads();

    if (tid < BM) {
        const int t = tid;
        float bv = L[t][0];
        int   bi = 0;
        #pragma unroll 8
        for (int e = 1; e < E; e++) {
            float v = L[t][e];
            if (v > bv) { bv = v; bi = e; }
        }
        float s = 0.0f;
        #pragma unroll 8
        for (int e = 0; e < E; e++) s += expf(L[t][e] - bv);
        float inv = 1.0f / s;
        smax[t] = bv;
        sinv[t] = inv;
        g_beste[m0 + t] = bi;
        g_gmax[m0 + t]  = inv;               // max gate = 1/sum
        atomicAdd(&scnt[bi], 1);
    }
    __syncthreads();
    if (tid < E) {
        const int e = tid;
        float me = 0.0f;
        #pragma unroll 8
        for (int t = 0; t < BM; t++)
            me += expf(L[t][e] - smax[t]) * sinv[t];
        g_me_part[blockIdx.x * E + e]  = me;
        g_cnt_part[blockIdx.x * E + e] = scnt[e];
    }
}

// ---------------------------------------------------------------------------
// K2: rank + position + histogram, full-chip parallel (128 blocks x 256 thr)
//   rank(t) = #{u: g[u] > g[t]} + #{u < t: g[u] == g[t]}   (exact stable rank)
// ---------------------------------------------------------------------------
__global__ void __launch_bounds__(256) k2_rankpos() {
    __shared__ float sh[S];              // 32 KB: all gmax
    __shared__ int   spcnt[4][65];
    const int tid = threadIdx.x;
    const int b   = blockIdx.x;
    for (int i = tid; i < S; i += 256) sh[i] = g_gmax[i];
    __syncthreads();

    const int tok  = tid & 63;
    const int part = tid >> 6;           // 0..3, constant within warp
    const int tg   = b * 64 + tok;
    const float gt = sh[tg];
    const int base = part * 2048;
    const int lo   = tg - base;          // u<tg  <=>  j<lo
    int cnt = 0;
    #pragma unroll 8
    for (int j = 0; j < 2048; j++) {
        float v = sh[base + j];
        cnt += (int)(v > gt) + (int)((j < lo) & (v == gt));
    }
    spcnt[part][tok] = cnt;
    __syncthreads();

    if (tid < 64) {
        int r = spcnt[0][tid] + spcnt[1][tid] + spcnt[2][tid] + spcnt[3][tid];
        const int t = b * 64 + tid;
        const int p = (r + SHIFT) & (S - 1);
        const int e = g_beste[t];
        g_expert_at_p[p] = e;
        g_token_at_p[p]  = t;
        atomicAdd(&g_hist[(p >> 6) * E + e], 1);
    }
}

// ---------------------------------------------------------------------------
// K3: block 0: per-expert capacity prefix -> release flag -> finalize.
//     blocks 1..8: wait flag, then ballot scatter (16 chunks each).
// ---------------------------------------------------------------------------
__global__ void __launch_bounds__(1024) k3_pfxscatfin(float* __restrict__ out) {
    const int tid = threadIdx.x;
    if (blockIdx.x == 0) {
        // ---- prefix: exclusive scan over 128 chunks per expert ----
        __shared__ int spart[4 * 64];
        const int e = tid & 63;
        const int q = (tid >> 6) & 3;
        int v[32];
        if (tid < 256) {
            int sum = 0;
            #pragma unroll
            for (int i = 0; i < 32; i++) {
                v[i] = g_hist[((q * 32 + i) << 6) + e];
                sum += v[i];
            }
            spart[q * 64 + e] = sum;
        }
        __syncthreads();
        if (tid < 256) {
            int run = 0;
            for (int qq = 0; qq < q; qq++) run += spart[qq * 64 + e];
            #pragma unroll
            for (int i = 0; i < 32; i++) {
                g_choff[((q * 32 + i) << 6) + e] = run;
                run += v[i];
            }
        }
        __threadfence();
        __syncthreads();
        if (tid == 0) atomicExch(&g_done, 1u);

        // ---- finalize: tree reduce of 256x64 partials ----
        __shared__ float sme[16][64];
        __shared__ int   scn[16][64];
        const int ee = tid & 63;
        const int g  = tid >> 6;             // 16 groups of 16 gemm blocks
        float me = 0.0f;
        int   c  = 0;
        #pragma unroll
        for (int i = 0; i < 16; i++) {
            int bb = g * 16 + i;
            me += g_me_part[bb * E + ee];
            c  += g_cnt_part[bb * E + ee];
        }
        sme[g][ee] = me;
        scn[g][ee] = c;
        __syncthreads();
        const float inv = 1.0f / (float)S;
        if (tid < E) {
            float m = 0.0f;
            int  cc = 0;
            #pragma unroll
            for (int gg = 0; gg < 16; gg++) { m += sme[gg][tid]; cc += scn[gg][tid]; }
            sme[0][tid] = (m * inv) * ((float)cc * inv);
            scn[0][tid] = cc;
            out[1LL + 2LL * SEC + tid] = (float)cc;
        }
        __syncthreads();
        if (tid == 0) {
            float sum = 0.0f;
            int dropped = 0;
            for (int k = 0; k < E; k++) {
                sum += sme[0][k];
                int d = scn[0][k] - CAP;
                if (d > 0) dropped += d;
            }
            out[0] = sum * (float)E * 0.01f;
            out[1LL + 2LL * SEC + E] = (float)dropped * inv;
        }
    } else {
        // ---- wait for prefix ----
        if (tid == 0) { while (atomicAdd(&g_done, 0u) == 0u) {} }
        __syncthreads();

        // ---- ballot scatter: 16 chunks of 64 per block ----
        __shared__ int h0[16 * 64];
        const int chunk = tid >> 6;           // 0..15
        const int lane  = tid & 31;
        const int half  = (tid >> 5) & 1;
        const int gchunk = (blockIdx.x - 1) * 16 + chunk;
        const int p = gchunk * 64 + (tid & 63);
        const int e = g_expert_at_p[p];
        const int t = g_token_at_p[p];
        h0[tid] = 0;
        __syncthreads();
        unsigned mask = __match_any_sync(0xffffffffu, e);
        int below = __popc(mask & ((1u << lane) - 1u));
        if (half == 0 && lane == (int)(__ffs(mask) - 1))
            h0[chunk * 64 + e] = __popc(mask);
        __syncthreads();
        int c = below + (half ? h0[chunk * 64 + e] : 0);
        const int loc = g_choff[gchunk * E + e] + c;
        if (loc < CAP) {
            long long base = 1LL + ((long long)t * E + e) * CAP + loc;
            out[base]       = g_gmax[t];   // combine_weights
            out[base + SEC] = 1.0f;        // dispatch_mask
        }
        __syncthreads();
        if (tid == 0) {
            unsigned d = atomicAdd(&g_c4, 1u);
            if (d == 7u) { g_done = 0; g_c4 = 0; }   // last scatter block resets
        }
    }
}

// ---------------------------------------------------------------------------
extern "C" void kernel_launch(void* const* d_in, const int* in_sizes, int n_in,
                              void* d_out, int out_size) {
    const float* x = (const float*)d_in[0];   // [S, D]
    const float* w = (const float*)d_in[1];   // [E, D]
    float* out = (float*)d_out;
    long long osz = (long long)out_size;

    k1_fused<<<GEMM_BLOCKS + ZERO_BLOCKS, 256>>>(x, w, out, osz);   // launch 0
    k2_rankpos<<<128, 256>>>();                                     // launch 1
    k3_pfxscatfin<<<9, 1024>>>(out);                                // launch 2
}

// round 13
// speedup vs baseline: 1.2101x; 1.2101x over previous
#include <cuda_runtime.h>
#include <cuda_bf16.h>
#include <cstdint>

// Problem constants
#define S 8192
#define D 1024
#define E 64
#define CAP 128
#define SHIFT 4096
static const long long SEC = (long long)S * E * CAP;   // 67108864

#define GEMM_BLOCKS 128
#define TFB 256                       // TMA fill blocks
#define CHUNK 32768LL                 // 32 KB per bulk store
#define NCHUNK 16383LL                // full 32KB chunks in 536,871,176 bytes
// tail floats [134209536, 134217794) filled by plain stores

// ---------------- scratch (device globals) ----------------------------------
__device__ int   g_beste[S];
__device__ float g_gmax[S];
__device__ int   g_expert_at_p[S];
__device__ int   g_token_at_p[S];
__device__ int   g_hist[S];          // zeroed in k1
__device__ int   g_choff[S];
__device__ float g_me_part[GEMM_BLOCKS * E];
__device__ int   g_cnt_part[GEMM_BLOCKS * E];
__device__ unsigned g_done, g_c4;    // k3 flag + reset counter (self-reset)

__device__ __forceinline__ uint32_t smem_u32(const void* p) {
    uint32_t a;
    asm("{ .reg .u64 t; cvta.to.shared.u64 t, %1; cvt.u32.u64 %0, t; }"
        : "=r"(a) : "l"(p));
    return a;
}

// ---------------------------------------------------------------------------
// K1: blocks 0..127 : GEMM (64 tokens x 64 experts) + softmax epilogue
//     blocks 128..  : TMA bulk-store zero-fill (32KB smem chunks -> gmem)
// ---------------------------------------------------------------------------
__global__ void __launch_bounds__(256)
k1_fused(const float* __restrict__ x, const float* __restrict__ w,
         float* __restrict__ out, long long out_size) {
    __shared__ float sbuf[8192];          // 32 KB (GEMM uses first 4160 floats)
    const int tid = threadIdx.x;

    if (blockIdx.x >= GEMM_BLOCKS) {
        // ---- TMA bulk-store fill ----
        const int fb = blockIdx.x - GEMM_BLOCKS;
        // zero own smem staging buffer
        for (int i = tid; i < 8192; i += 256) sbuf[i] = 0.0f;
        __syncthreads();
        if (tid == 0) {
            asm volatile("fence.proxy.async.shared::cta;" ::: "memory");
            const uint32_t saddr = smem_u32(sbuf);
            uint64_t gbase = (uint64_t)out;
            int inflight = 0;
            for (long long c = fb; c < NCHUNK; c += TFB) {
                uint64_t dst = gbase + (uint64_t)c * CHUNK;
                asm volatile(
                    "cp.async.bulk.global.shared::cta.bulk_group [%0], [%1], %2;"
                    :: "l"(dst), "r"(saddr), "r"((uint32_t)CHUNK) : "memory");
                asm volatile("cp.async.bulk.commit_group;" ::: "memory");
                if (++inflight >= 8) {
                    asm volatile("cp.async.bulk.wait_group 4;" ::: "memory");
                    inflight = 5;
                }
            }
            asm volatile("cp.async.bulk.wait_group 0;" ::: "memory");
        }
        // first fill block: scalar tail + hist zero (plain stores)
        if (fb == 0) {
            for (long long i = NCHUNK * (CHUNK / 4) + tid; i < out_size; i += 256)
                out[i] = 0.0f;
            for (int i = tid; i < S; i += 256) g_hist[i] = 0;
        }
        return;
    }

    // ---- GEMM: BM=64, BN=64, BK=32, 256 thr, 4x4 micro-tile (R11 proven) ----
    float (*As)[64] = (float(*)[64])sbuf;          // [32][64]
    float (*Bs)[64] = (float(*)[64])(sbuf + 2048); // [32][64]
    __shared__ float smax[64], sinv[64];
    __shared__ int   scnt[E];

    const int m0 = blockIdx.x * 64;
    const int tx = tid & 15;
    const int ty = tid >> 4;
    float acc[4][4];
    #pragma unroll
    for (int i = 0; i < 4; i++)
        #pragma unroll
        for (int j = 0; j < 4; j++) acc[i][j] = 0.0f;

    for (int k0 = 0; k0 < D; k0 += 32) {
        #pragma unroll
        for (int r = 0; r < 8; r++) {
            int l  = tid + r * 256;
            int mm = l & 63;
            int kk = l >> 6;
            As[kk][mm] = x[(long long)(m0 + mm) * D + k0 + kk];
            Bs[kk][mm] = w[(long long)mm * D + k0 + kk];
        }
        __syncthreads();
        #pragma unroll
        for (int kk = 0; kk < 32; kk++) {
            const float4 a = *(const float4*)(&As[kk][ty * 4]);
            const float4 b = *(const float4*)(&Bs[kk][tx * 4]);
            float av[4] = {a.x, a.y, a.z, a.w};
            float bv[4] = {b.x, b.y, b.z, b.w};
            #pragma unroll
            for (int i = 0; i < 4; i++)
                #pragma unroll
                for (int j = 0; j < 4; j++)
                    acc[i][j] += av[i] * bv[j];
        }
        __syncthreads();
    }

    float* L = sbuf;                           // [64][65] padded
    #pragma unroll
    for (int i = 0; i < 4; i++)
        #pragma unroll
        for (int j = 0; j < 4; j++)
            L[(ty * 4 + i) * 65 + tx * 4 + j] = acc[i][j];
    if (tid < E) scnt[tid] = 0;
    __syncthreads();

    if (tid < 64) {
        const int t = tid;
        float bv = L[t * 65];
        int   bi = 0;
        #pragma unroll 8
        for (int e = 1; e < E; e++) {
            float v = L[t * 65 + e];
            if (v > bv) { bv = v; bi = e; }
        }
        float s = 0.0f;
        #pragma unroll 8
        for (int e = 0; e < E; e++) s += expf(L[t * 65 + e] - bv);
        float inv = 1.0f / s;
        smax[t] = bv;
        sinv[t] = inv;
        g_beste[m0 + t] = bi;
        g_gmax[m0 + t]  = inv;                 // max gate = 1/sum
        atomicAdd(&scnt[bi], 1);
    }
    __syncthreads();
    if (tid < E) {
        const int e = tid;
        float me = 0.0f;
        #pragma unroll 8
        for (int t = 0; t < 64; t++)
            me += expf(L[t * 65 + e] - smax[t]) * sinv[t];
        g_me_part[blockIdx.x * E + e]  = me;
        g_cnt_part[blockIdx.x * E + e] = scnt[e];
    }
}

// ---------------------------------------------------------------------------
// K2: rank + position + histogram, full-chip parallel (128 blocks x 256 thr)
//   rank(t) = #{u: g[u] > g[t]} + #{u < t: g[u] == g[t]}   (exact stable rank)
// ---------------------------------------------------------------------------
__global__ void __launch_bounds__(256) k2_rankpos() {
    __shared__ float sh[S];              // 32 KB: all gmax
    __shared__ int   spcnt[4][65];
    const int tid = threadIdx.x;
    const int b   = blockIdx.x;
    for (int i = tid; i < S; i += 256) sh[i] = g_gmax[i];
    __syncthreads();

    const int tok  = tid & 63;
    const int part = tid >> 6;           // 0..3, constant within warp
    const int tg   = b * 64 + tok;
    const float gt = sh[tg];
    const int base = part * 2048;
    const int lo   = tg - base;          // u<tg  <=>  j<lo
    int cnt = 0;
    #pragma unroll 8
    for (int j = 0; j < 2048; j++) {
        float v = sh[base + j];
        cnt += (int)(v > gt) + (int)((j < lo) & (v == gt));
    }
    spcnt[part][tok] = cnt;
    __syncthreads();

    if (tid < 64) {
        int r = spcnt[0][tid] + spcnt[1][tid] + spcnt[2][tid] + spcnt[3][tid];
        const int t = b * 64 + tid;
        const int p = (r + SHIFT) & (S - 1);
        const int e = g_beste[t];
        g_expert_at_p[p] = e;
        g_token_at_p[p]  = t;
        atomicAdd(&g_hist[(p >> 6) * E + e], 1);
    }
}

// ---------------------------------------------------------------------------
// K3: block 0: per-expert capacity prefix -> release flag -> finalize.
//     blocks 1..8: wait flag, then ballot scatter (16 chunks each).
// ---------------------------------------------------------------------------
__global__ void __launch_bounds__(1024) k3_pfxscatfin(float* __restrict__ out) {
    const int tid = threadIdx.x;
    if (blockIdx.x == 0) {
        // ---- prefix: exclusive scan over 128 chunks per expert ----
        __shared__ int spart[4 * 64];
        const int e = tid & 63;
        const int q = (tid >> 6) & 3;
        int v[32];
        if (tid < 256) {
            int sum = 0;
            #pragma unroll
            for (int i = 0; i < 32; i++) {
                v[i] = g_hist[((q * 32 + i) << 6) + e];
                sum += v[i];
            }
            spart[q * 64 + e] = sum;
        }
        __syncthreads();
        if (tid < 256) {
            int run = 0;
            for (int qq = 0; qq < q; qq++) run += spart[qq * 64 + e];
            #pragma unroll
            for (int i = 0; i < 32; i++) {
                g_choff[((q * 32 + i) << 6) + e] = run;
                run += v[i];
            }
        }
        __threadfence();
        __syncthreads();
        if (tid == 0) atomicExch(&g_done, 1u);

        // ---- finalize: tree reduce of 128x64 partials ----
        __shared__ float sme[16][64];
        __shared__ int   scn[16][64];
        const int ee = tid & 63;
        const int g  = tid >> 6;             // 16 groups of 8 gemm blocks
        float me = 0.0f;
        int   c  = 0;
        #pragma unroll
        for (int i = 0; i < 8; i++) {
            int bb = g * 8 + i;
            me += g_me_part[bb * E + ee];
            c  += g_cnt_part[bb * E + ee];
        }
        sme[g][ee] = me;
        scn[g][ee] = c;
        __syncthreads();
        const float inv = 1.0f / (float)S;
        if (tid < E) {
            float m = 0.0f;
            int  cc = 0;
            #pragma unroll
            for (int gg = 0; gg < 16; gg++) { m += sme[gg][tid]; cc += scn[gg][tid]; }
            sme[0][tid] = (m * inv) * ((float)cc * inv);
            scn[0][tid] = cc;
            out[1LL + 2LL * SEC + tid] = (float)cc;
        }
        __syncthreads();
        if (tid == 0) {
            float sum = 0.0f;
            int dropped = 0;
            for (int k = 0; k < E; k++) {
                sum += sme[0][k];
                int d = scn[0][k] - CAP;
                if (d > 0) dropped += d;
            }
            out[0] = sum * (float)E * 0.01f;
            out[1LL + 2LL * SEC + E] = (float)dropped * inv;
        }
    } else {
        // ---- wait for prefix ----
        if (tid == 0) { while (atomicAdd(&g_done, 0u) == 0u) {} }
        __syncthreads();

        // ---- ballot scatter: 16 chunks of 64 per block ----
        __shared__ int h0[16 * 64];
        const int chunk = tid >> 6;           // 0..15
        const int lane  = tid & 31;
        const int half  = (tid >> 5) & 1;
        const int gchunk = (blockIdx.x - 1) * 16 + chunk;
        const int p = gchunk * 64 + (tid & 63);
        const int e = g_expert_at_p[p];
        const int t = g_token_at_p[p];
        h0[tid] = 0;
        __syncthreads();
        unsigned mask = __match_any_sync(0xffffffffu, e);
        int below = __popc(mask & ((1u << lane) - 1u));
        if (half == 0 && lane == (int)(__ffs(mask) - 1))
            h0[chunk * 64 + e] = __popc(mask);
        __syncthreads();
        int c = below + (half ? h0[chunk * 64 + e] : 0);
        const int loc = g_choff[gchunk * E + e] + c;
        if (loc < CAP) {
            long long base = 1LL + ((long long)t * E + e) * CAP + loc;
            out[base]       = g_gmax[t];   // combine_weights
            out[base + SEC] = 1.0f;        // dispatch_mask
        }
        __syncthreads();
        if (tid == 0) {
            unsigned d = atomicAdd(&g_c4, 1u);
            if (d == 7u) { g_done = 0; g_c4 = 0; }   // last scatter block resets
        }
    }
}

// ---------------------------------------------------------------------------
extern "C" void kernel_launch(void* const* d_in, const int* in_sizes, int n_in,
                              void* d_out, int out_size) {
    const float* x = (const float*)d_in[0];   // [S, D]
    const float* w = (const float*)d_in[1];   // [E, D]
    float* out = (float*)d_out;
    long long osz = (long long)out_size;

    k1_fused<<<GEMM_BLOCKS + TFB, 256>>>(x, w, out, osz);   // launch 0
    k2_rankpos<<<128, 256>>>();                             // launch 1
    k3_pfxscatfin<<<9, 1024>>>(out);                        // launch 2
}

// round 14
// speedup vs baseline: 1.2312x; 1.0174x over previous
#include <cuda_runtime.h>
#include <cuda_bf16.h>
#include <cstdint>

// Problem constants
#define S 8192
#define D 1024
#define E 64
#define CAP 128
#define SHIFT 4096
static const long long SEC = (long long)S * E * CAP;   // 67108864

#define GEMM_BLOCKS 128
#define TFB 256                       // TMA fill blocks
#define CHUNK 32768LL                 // 32 KB per bulk store
#define NCHUNK 16383LL                // full 32KB chunks in 536,871,176 bytes

// ---------------- scratch (device globals) ----------------------------------
__device__ int   g_beste[S];
__device__ float g_gmax[S];
__device__ int   g_expert_at_p[S];
__device__ int   g_token_at_p[S];
__device__ int   g_hist[S];          // zeroed in k1
__device__ int   g_choff[S];
__device__ float g_me_part[GEMM_BLOCKS * E];
__device__ int   g_cnt_part[GEMM_BLOCKS * E];
__device__ unsigned g_rankdone, g_done, g_c4;   // flags; self-resetting

__device__ __forceinline__ uint32_t smem_u32(const void* p) {
    uint32_t a;
    asm("{ .reg .u64 t; cvta.to.shared.u64 t, %1; cvt.u32.u64 %0, t; }"
        : "=r"(a) : "l"(p));
    return a;
}

// ---------------------------------------------------------------------------
// K1: blocks 0..127 : GEMM (64 tokens x 64 experts) + softmax epilogue
//     blocks 128..  : TMA bulk-store zero-fill (32KB smem chunks -> gmem)
// ---------------------------------------------------------------------------
__global__ void __launch_bounds__(256)
k1_fused(const float* __restrict__ x, const float* __restrict__ w,
         float* __restrict__ out, long long out_size) {
    __shared__ float sbuf[8192];          // 32 KB (GEMM uses first 4160 floats)
    const int tid = threadIdx.x;

    if (blockIdx.x >= GEMM_BLOCKS) {
        // ---- TMA bulk-store fill ----
        const int fb = blockIdx.x - GEMM_BLOCKS;
        for (int i = tid; i < 8192; i += 256) sbuf[i] = 0.0f;
        __syncthreads();
        if (tid == 0) {
            asm volatile("fence.proxy.async.shared::cta;" ::: "memory");
            const uint32_t saddr = smem_u32(sbuf);
            uint64_t gbase = (uint64_t)out;
            int inflight = 0;
            for (long long c = fb; c < NCHUNK; c += TFB) {
                uint64_t dst = gbase + (uint64_t)c * CHUNK;
                asm volatile(
                    "cp.async.bulk.global.shared::cta.bulk_group [%0], [%1], %2;"
                    :: "l"(dst), "r"(saddr), "r"((uint32_t)CHUNK) : "memory");
                asm volatile("cp.async.bulk.commit_group;" ::: "memory");
                if (++inflight >= 8) {
                    asm volatile("cp.async.bulk.wait_group 4;" ::: "memory");
                    inflight = 5;
                }
            }
            asm volatile("cp.async.bulk.wait_group 0;" ::: "memory");
        }
        if (fb == 0) {
            for (long long i = NCHUNK * (CHUNK / 4) + tid; i < out_size; i += 256)
                out[i] = 0.0f;
            for (int i = tid; i < S; i += 256) g_hist[i] = 0;
        }
        return;
    }

    // ---- GEMM: BM=64, BN=64, BK=32, 256 thr, 4x4 micro-tile ----
    float (*As)[64] = (float(*)[64])sbuf;          // [32][64]
    float (*Bs)[64] = (float(*)[64])(sbuf + 2048); // [32][64]
    __shared__ float smax[64], sinv[64];
    __shared__ int   scnt[E];

    const int m0 = blockIdx.x * 64;
    const int tx = tid & 15;
    const int ty = tid >> 4;
    float acc[4][4];
    #pragma unroll
    for (int i = 0; i < 4; i++)
        #pragma unroll
        for (int j = 0; j < 4; j++) acc[i][j] = 0.0f;

    for (int k0 = 0; k0 < D; k0 += 32) {
        #pragma unroll
        for (int r = 0; r < 8; r++) {
            int l  = tid + r * 256;
            int mm = l & 63;
            int kk = l >> 6;
            As[kk][mm] = x[(long long)(m0 + mm) * D + k0 + kk];
            Bs[kk][mm] = w[(long long)mm * D + k0 + kk];
        }
        __syncthreads();
        #pragma unroll
        for (int kk = 0; kk < 32; kk++) {
            const float4 a = *(const float4*)(&As[kk][ty * 4]);
            const float4 b = *(const float4*)(&Bs[kk][tx * 4]);
            float av[4] = {a.x, a.y, a.z, a.w};
            float bv[4] = {b.x, b.y, b.z, b.w};
            #pragma unroll
            for (int i = 0; i < 4; i++)
                #pragma unroll
                for (int j = 0; j < 4; j++)
                    acc[i][j] += av[i] * bv[j];
        }
        __syncthreads();
    }

    float* L = sbuf;                           // [64][65] padded
    #pragma unroll
    for (int i = 0; i < 4; i++)
        #pragma unroll
        for (int j = 0; j < 4; j++)
            L[(ty * 4 + i) * 65 + tx * 4 + j] = acc[i][j];
    if (tid < E) scnt[tid] = 0;
    __syncthreads();

    if (tid < 64) {
        const int t = tid;
        float bv = L[t * 65];
        int   bi = 0;
        #pragma unroll 8
        for (int e = 1; e < E; e++) {
            float v = L[t * 65 + e];
            if (v > bv) { bv = v; bi = e; }
        }
        float s = 0.0f;
        #pragma unroll 8
        for (int e = 0; e < E; e++) s += expf(L[t * 65 + e] - bv);
        float inv = 1.0f / s;
        smax[t] = bv;
        sinv[t] = inv;
        g_beste[m0 + t] = bi;
        g_gmax[m0 + t]  = inv;                 // max gate = 1/sum
        atomicAdd(&scnt[bi], 1);
    }
    __syncthreads();
    if (tid < E) {
        const int e = tid;
        float me = 0.0f;
        #pragma unroll 8
        for (int t = 0; t < 64; t++)
            me += expf(L[t * 65 + e] - smax[t]) * sinv[t];
        g_me_part[blockIdx.x * E + e]  = me;
        g_cnt_part[blockIdx.x * E + e] = scnt[e];
    }
}

// ---------------------------------------------------------------------------
// kT: entire tail in one launch. 137 blocks x 1024 threads (all resident).
//   blocks 0..127 : rank (16 slices/token) + position + hist -> arrive
//   block 128     : wait all ranks -> prefix -> g_done -> finalize
//   blocks 129..136: wait g_done -> ballot scatter (16 chunks each)
// ---------------------------------------------------------------------------
__global__ void __launch_bounds__(1024) kT(float* __restrict__ out) {
    __shared__ uint32_t smu[9232];            // 36.9 KB, aliased per role
    const int tid = threadIdx.x;
    const int b   = blockIdx.x;

    if (b < 128) {
        // ---- rank + position + histogram ----
        float* sh   = (float*)smu;            // [8192]
        int* spcnt  = (int*)(smu + 8192);     // [16*64]
        for (int i = tid; i < S; i += 1024) sh[i] = g_gmax[i];
        __syncthreads();

        const int tok  = tid & 63;
        const int part = tid >> 6;            // 0..15, warp-uniform
        const int tg   = b * 64 + tok;
        const float gt = sh[tg];
        const int base = part * 512;
        int cnt = 0;
        #pragma unroll 8
        for (int j = 0; j < 512; j++) {
            int u = base + j;
            float v = sh[u];
            cnt += (int)(v > gt) + (int)((u < tg) & (v == gt));
        }
        spcnt[part * 64 + tok] = cnt;
        __syncthreads();

        if (tid < 64) {
            int r = 0;
            #pragma unroll
            for (int p = 0; p < 16; p++) r += spcnt[p * 64 + tid];
            const int t = b * 64 + tid;
            const int p = (r + SHIFT) & (S - 1);
            const int e = g_beste[t];
            g_expert_at_p[p] = e;
            g_token_at_p[p]  = t;
            atomicAdd(&g_hist[(p >> 6) * E + e], 1);
        }
        __threadfence();
        __syncthreads();
        if (tid == 0) atomicAdd(&g_rankdone, 1u);
    } else if (b == 128) {
        // ---- wait for all rank blocks ----
        if (tid == 0) { while (atomicAdd(&g_rankdone, 0u) < 128u) {} }
        __syncthreads();

        // ---- prefix: per-expert exclusive scan over 128 chunks ----
        int* spart = (int*)smu;               // [256]
        const int e = tid & 63;
        const int q = (tid >> 6) & 3;
        int v[32];
        if (tid < 256) {
            int sum = 0;
            #pragma unroll
            for (int i = 0; i < 32; i++) {
                v[i] = __ldcg(&g_hist[((q * 32 + i) << 6) + e]);
                sum += v[i];
            }
            spart[q * 64 + e] = sum;
        }
        __syncthreads();
        if (tid < 256) {
            int run = 0;
            for (int qq = 0; qq < q; qq++) run += spart[qq * 64 + e];
            #pragma unroll
            for (int i = 0; i < 32; i++) {
                g_choff[((q * 32 + i) << 6) + e] = run;
                run += v[i];
            }
        }
        __threadfence();
        __syncthreads();
        if (tid == 0) atomicExch(&g_done, 1u);

        // ---- finalize: tree reduce of 128x64 partials ----
        float (*sme)[64] = (float(*)[64])smu;            // 16x64 f
        int   (*scn)[64] = (int(*)[64])(smu + 1024);     // 16x64 i
        const int ee = tid & 63;
        const int g  = tid >> 6;             // 16 groups of 8 gemm blocks
        float me = 0.0f;
        int   c  = 0;
        #pragma unroll
        for (int i = 0; i < 8; i++) {
            int bb = g * 8 + i;
            me += g_me_part[bb * E + ee];
            c  += g_cnt_part[bb * E + ee];
        }
        __syncthreads();                      // spart dead before sme reuse
        sme[g][ee] = me;
        scn[g][ee] = c;
        __syncthreads();
        const float inv = 1.0f / (float)S;
        if (tid < E) {
            float m = 0.0f;
            int  cc = 0;
            #pragma unroll
            for (int gg = 0; gg < 16; gg++) { m += sme[gg][tid]; cc += scn[gg][tid]; }
            sme[0][tid] = (m * inv) * ((float)cc * inv);
            scn[0][tid] = cc;
            out[1LL + 2LL * SEC + tid] = (float)cc;
        }
        __syncthreads();
        if (tid == 0) {
            float sum = 0.0f;
            int dropped = 0;
            for (int k = 0; k < E; k++) {
                sum += sme[0][k];
                int d = scn[0][k] - CAP;
                if (d > 0) dropped += d;
            }
            out[0] = sum * (float)E * 0.01f;
            out[1LL + 2LL * SEC + E] = (float)dropped * inv;
        }
    } else {
        // ---- wait for prefix ----
        if (tid == 0) { while (atomicAdd(&g_done, 0u) == 0u) {} }
        __syncthreads();

        // ---- ballot scatter: 16 chunks of 64 per block ----
        int* h0 = (int*)smu;                  // [16*64]
        const int chunk = tid >> 6;           // 0..15
        const int lane  = tid & 31;
        const int half  = (tid >> 5) & 1;
        const int gchunk = (b - 129) * 16 + chunk;
        const int p = gchunk * 64 + (tid & 63);
        const int e = __ldcg(&g_expert_at_p[p]);
        const int t = __ldcg(&g_token_at_p[p]);
        h0[tid] = 0;
        __syncthreads();
        unsigned mask = __match_any_sync(0xffffffffu, e);
        int below = __popc(mask & ((1u << lane) - 1u));
        if (half == 0 && lane == (int)(__ffs(mask) - 1))
            h0[chunk * 64 + e] = __popc(mask);
        __syncthreads();
        int c = below + (half ? h0[chunk * 64 + e] : 0);
        const int loc = __ldcg(&g_choff[gchunk * E + e]) + c;
        if (loc < CAP) {
            long long base = 1LL + ((long long)t * E + e) * CAP + loc;
            out[base]       = g_gmax[t];   // combine_weights
            out[base + SEC] = 1.0f;        // dispatch_mask
        }
        __syncthreads();
        if (tid == 0) {
            unsigned d = atomicAdd(&g_c4, 1u);
            if (d == 7u) { g_done = 0; g_c4 = 0; g_rankdone = 0; }  // reset
        }
    }
}

// ---------------------------------------------------------------------------
extern "C" void kernel_launch(void* const* d_in, const int* in_sizes, int n_in,
                              void* d_out, int out_size) {
    const float* x = (const float*)d_in[0];   // [S, D]
    const float* w = (const float*)d_in[1];   // [E, D]
    float* out = (float*)d_out;
    long long osz = (long long)out_size;

    k1_fused<<<GEMM_BLOCKS + TFB, 256>>>(x, w, out, osz);   // launch 0
    kT<<<137, 1024>>>(out);                                 // launch 1
}

// round 15
// speedup vs baseline: 1.2777x; 1.0378x over previous
#include <cuda_runtime.h>
#include <cuda_bf16.h>
#include <cstdint>

// Problem constants
#define S 8192
#define D 1024
#define E 64
#define CAP 128
#define SHIFT 4096
static const long long SEC = (long long)S * E * CAP;   // 67108864

#define GEMM_BLOCKS 128
#define TFB 256                       // TMA fill blocks
#define CHUNK 32768LL                 // 32 KB per bulk store
#define NCHUNK 16383LL                // full 32KB chunks in 536,871,176 bytes

// ---------------- scratch (device globals) ----------------------------------
__device__ int   g_beste[S];
__device__ float g_gmax[S];
__device__ int   g_expert_at_p[S];
__device__ int   g_token_at_p[S];
__device__ int   g_hist[S];          // zeroed in k1
__device__ int   g_choff[S];
__device__ float g_me_part[GEMM_BLOCKS * E];
__device__ int   g_cnt_part[GEMM_BLOCKS * E];
__device__ unsigned g_rankdone, g_done, g_c4;   // flags; self-resetting

__device__ __forceinline__ uint32_t smem_u32(const void* p) {
    uint32_t a;
    asm("{ .reg .u64 t; cvta.to.shared.u64 t, %1; cvt.u32.u64 %0, t; }"
        : "=r"(a) : "l"(p));
    return a;
}

// ---------------------------------------------------------------------------
// K1: blocks 0..127 : GEMM (64 tokens x 64 experts) + softmax epilogue
//     blocks 128..  : TMA bulk-store zero-fill (32KB smem chunks -> gmem)
// ---------------------------------------------------------------------------
__global__ void __launch_bounds__(256)
k1_fused(const float* __restrict__ x, const float* __restrict__ w,
         float* __restrict__ out, long long out_size) {
    __shared__ float sbuf[8192];          // 32 KB (GEMM uses first 4160 floats)
    const int tid = threadIdx.x;

    if (blockIdx.x >= GEMM_BLOCKS) {
        // ---- TMA bulk-store fill ----
        const int fb = blockIdx.x - GEMM_BLOCKS;
        for (int i = tid; i < 8192; i += 256) sbuf[i] = 0.0f;
        __syncthreads();
        if (tid == 0) {
            asm volatile("fence.proxy.async.shared::cta;" ::: "memory");
            const uint32_t saddr = smem_u32(sbuf);
            uint64_t gbase = (uint64_t)out;
            int inflight = 0;
            for (long long c = fb; c < NCHUNK; c += TFB) {
                uint64_t dst = gbase + (uint64_t)c * CHUNK;
                asm volatile(
                    "cp.async.bulk.global.shared::cta.bulk_group [%0], [%1], %2;"
                    :: "l"(dst), "r"(saddr), "r"((uint32_t)CHUNK) : "memory");
                asm volatile("cp.async.bulk.commit_group;" ::: "memory");
                if (++inflight >= 8) {
                    asm volatile("cp.async.bulk.wait_group 4;" ::: "memory");
                    inflight = 5;
                }
            }
            asm volatile("cp.async.bulk.wait_group 0;" ::: "memory");
        }
        if (fb == 0) {
            for (long long i = NCHUNK * (CHUNK / 4) + tid; i < out_size; i += 256)
                out[i] = 0.0f;
            for (int i = tid; i < S; i += 256) g_hist[i] = 0;
        }
        return;
    }

    // ---- GEMM: BM=64, BN=64, BK=32, 256 thr, 4x4 micro-tile ----
    float (*As)[64] = (float(*)[64])sbuf;          // [32][64]
    float (*Bs)[64] = (float(*)[64])(sbuf + 2048); // [32][64]
    __shared__ float smax[64], sinv[64];
    __shared__ int   scnt[E];

    const int m0 = blockIdx.x * 64;
    const int tx = tid & 15;
    const int ty = tid >> 4;
    float acc[4][4];
    #pragma unroll
    for (int i = 0; i < 4; i++)
        #pragma unroll
        for (int j = 0; j < 4; j++) acc[i][j] = 0.0f;

    for (int k0 = 0; k0 < D; k0 += 32) {
        #pragma unroll
        for (int r = 0; r < 8; r++) {
            int l  = tid + r * 256;
            int mm = l & 63;
            int kk = l >> 6;
            As[kk][mm] = x[(long long)(m0 + mm) * D + k0 + kk];
            Bs[kk][mm] = w[(long long)mm * D + k0 + kk];
        }
        __syncthreads();
        #pragma unroll
        for (int kk = 0; kk < 32; kk++) {
            const float4 a = *(const float4*)(&As[kk][ty * 4]);
            const float4 b = *(const float4*)(&Bs[kk][tx * 4]);
            float av[4] = {a.x, a.y, a.z, a.w};
            float bv[4] = {b.x, b.y, b.z, b.w};
            #pragma unroll
            for (int i = 0; i < 4; i++)
                #pragma unroll
                for (int j = 0; j < 4; j++)
                    acc[i][j] += av[i] * bv[j];
        }
        __syncthreads();
    }

    float* L = sbuf;                           // [64][65] padded
    #pragma unroll
    for (int i = 0; i < 4; i++)
        #pragma unroll
        for (int j = 0; j < 4; j++)
            L[(ty * 4 + i) * 65 + tx * 4 + j] = acc[i][j];
    if (tid < E) scnt[tid] = 0;
    __syncthreads();

    if (tid < 64) {
        const int t = tid;
        float bv = L[t * 65];
        int   bi = 0;
        #pragma unroll 8
        for (int e = 1; e < E; e++) {
            float v = L[t * 65 + e];
            if (v > bv) { bv = v; bi = e; }
        }
        float s = 0.0f;
        #pragma unroll 8
        for (int e = 0; e < E; e++) s += expf(L[t * 65 + e] - bv);
        float inv = 1.0f / s;
        smax[t] = bv;
        sinv[t] = inv;
        g_beste[m0 + t] = bi;
        g_gmax[m0 + t]  = inv;                 // max gate = 1/sum
        atomicAdd(&scnt[bi], 1);
    }
    __syncthreads();
    if (tid < E) {
        const int e = tid;
        float me = 0.0f;
        #pragma unroll 8
        for (int t = 0; t < 64; t++)
            me += expf(L[t * 65 + e] - smax[t]) * sinv[t];
        g_me_part[blockIdx.x * E + e]  = me;
        g_cnt_part[blockIdx.x * E + e] = scnt[e];
    }
}

// ---------------------------------------------------------------------------
// kT: entire tail in one launch. 137 blocks x 1024 threads (all resident).
//   blocks 0..127 : rank (16 slices/token, split-loop + float4) + pos + hist
//   block 128     : wait all ranks -> prefix -> g_done -> finalize
//   blocks 129..136: wait g_done -> ballot scatter (16 chunks each)
// ---------------------------------------------------------------------------
__global__ void __launch_bounds__(1024) kT(float* __restrict__ out) {
    __shared__ uint32_t smu[9232];            // 36.9 KB, aliased per role
    const int tid = threadIdx.x;
    const int b   = blockIdx.x;

    if (b < 128) {
        // ---- rank + position + histogram ----
        float* sh   = (float*)smu;            // [8192]
        int* spcnt  = (int*)(smu + 8192);     // [16*64]
        for (int i = tid; i < S; i += 1024) sh[i] = g_gmax[i];
        __syncthreads();

        // rank(t) = #{u<t: v>=gt} + #{u>t: v>gt}; boundary slice pb = b>>3
        // holds ALL this block's tokens (b*64..b*64+63 within [pb*512,pb*512+512)).
        const int tok  = tid & 63;
        const int part = tid >> 6;            // 0..15, warp-uniform
        const int tg   = b * 64 + tok;
        const float gt = sh[tg];
        const int pb   = b >> 3;
        int cnt = 0;
        if (part != pb) {
            const float4* s4 = (const float4*)(sh + part * 512);
            if (part < pb) {                  // all u < tg: count >=
                #pragma unroll 8
                for (int j = 0; j < 128; j++) {
                    float4 v = s4[j];
                    cnt += (int)(v.x >= gt) + (int)(v.y >= gt)
                         + (int)(v.z >= gt) + (int)(v.w >= gt);
                }
            } else {                          // all u > tg: count >
                #pragma unroll 8
                for (int j = 0; j < 128; j++) {
                    float4 v = s4[j];
                    cnt += (int)(v.x > gt) + (int)(v.y > gt)
                         + (int)(v.z > gt) + (int)(v.w > gt);
                }
            }
        } else {
            const int base = part * 512;
            const int split = tg - base;      // u<tg for j<split
            #pragma unroll 4
            for (int j = 0; j < 512; j++) {
                float v = sh[base + j];
                cnt += (j < split) ? (int)(v >= gt) : (int)(v > gt);
            }
        }
        spcnt[part * 64 + tok] = cnt;
        __syncthreads();

        if (tid < 64) {
            int r = 0;
            #pragma unroll
            for (int p = 0; p < 16; p++) r += spcnt[p * 64 + tid];
            const int t = b * 64 + tid;
            const int p = (r + SHIFT) & (S - 1);
            const int e = g_beste[t];
            g_expert_at_p[p] = e;
            g_token_at_p[p]  = t;
            atomicAdd(&g_hist[(p >> 6) * E + e], 1);
        }
        __threadfence();
        __syncthreads();
        if (tid == 0) atomicAdd(&g_rankdone, 1u);
    } else if (b == 128) {
        // ---- wait for all rank blocks ----
        if (tid == 0) { while (atomicAdd(&g_rankdone, 0u) < 128u) {} }
        __syncthreads();

        // ---- prefix: per-expert exclusive scan over 128 chunks ----
        int* spart = (int*)smu;               // [256]
        const int e = tid & 63;
        const int q = (tid >> 6) & 3;
        int v[32];
        if (tid < 256) {
            int sum = 0;
            #pragma unroll
            for (int i = 0; i < 32; i++) {
                v[i] = __ldcg(&g_hist[((q * 32 + i) << 6) + e]);
                sum += v[i];
            }
            spart[q * 64 + e] = sum;
        }
        __syncthreads();
        if (tid < 256) {
            int run = 0;
            for (int qq = 0; qq < q; qq++) run += spart[qq * 64 + e];
            #pragma unroll
            for (int i = 0; i < 32; i++) {
                g_choff[((q * 32 + i) << 6) + e] = run;
                run += v[i];
            }
        }
        __threadfence();
        __syncthreads();
        if (tid == 0) atomicExch(&g_done, 1u);

        // ---- finalize: tree reduce of 128x64 partials ----
        float (*sme)[64] = (float(*)[64])smu;            // 16x64 f
        int   (*scn)[64] = (int(*)[64])(smu + 1024);     // 16x64 i
        const int ee = tid & 63;
        const int g  = tid >> 6;             // 16 groups of 8 gemm blocks
        float me = 0.0f;
        int   c  = 0;
        #pragma unroll
        for (int i = 0; i < 8; i++) {
            int bb = g * 8 + i;
            me += g_me_part[bb * E + ee];
            c  += g_cnt_part[bb * E + ee];
        }
        __syncthreads();                      // spart dead before sme reuse
        sme[g][ee] = me;
        scn[g][ee] = c;
        __syncthreads();
        const float inv = 1.0f / (float)S;
        if (tid < E) {
            float m = 0.0f;
            int  cc = 0;
            #pragma unroll
            for (int gg = 0; gg < 16; gg++) { m += sme[gg][tid]; cc += scn[gg][tid]; }
            sme[0][tid] = (m * inv) * ((float)cc * inv);
            scn[0][tid] = cc;
            out[1LL + 2LL * SEC + tid] = (float)cc;
        }
        __syncthreads();
        if (tid == 0) {
            float sum = 0.0f;
            int dropped = 0;
            for (int k = 0; k < E; k++) {
                sum += sme[0][k];
                int d = scn[0][k] - CAP;
                if (d > 0) dropped += d;
            }
            out[0] = sum * (float)E * 0.01f;
            out[1LL + 2LL * SEC + E] = (float)dropped * inv;
        }
    } else {
        // ---- wait for prefix ----
        if (tid == 0) { while (atomicAdd(&g_done, 0u) == 0u) {} }
        __syncthreads();

        // ---- ballot scatter: 16 chunks of 64 per block ----
        int* h0 = (int*)smu;                  // [16*64]
        const int chunk = tid >> 6;           // 0..15
        const int lane  = tid & 31;
        const int half  = (tid >> 5) & 1;
        const int gchunk = (b - 129) * 16 + chunk;
        const int p = gchunk * 64 + (tid & 63);
        const int e = __ldcg(&g_expert_at_p[p]);
        const int t = __ldcg(&g_token_at_p[p]);
        h0[tid] = 0;
        __syncthreads();
        unsigned mask = __match_any_sync(0xffffffffu, e);
        int below = __popc(mask & ((1u << lane) - 1u));
        if (half == 0 && lane == (int)(__ffs(mask) - 1))
            h0[chunk * 64 + e] = __popc(mask);
        __syncthreads();
        int c = below + (half ? h0[chunk * 64 + e] : 0);
        const int loc = __ldcg(&g_choff[gchunk * E + e]) + c;
        if (loc < CAP) {
            long long base = 1LL + ((long long)t * E + e) * CAP + loc;
            out[base]       = g_gmax[t];   // combine_weights
            out[base + SEC] = 1.0f;        // dispatch_mask
        }
        __syncthreads();
        if (tid == 0) {
            unsigned d = atomicAdd(&g_c4, 1u);
            if (d == 7u) { g_done = 0; g_c4 = 0; g_rankdone = 0; }  // reset
        }
    }
}

// ---------------------------------------------------------------------------
extern "C" void kernel_launch(void* const* d_in, const int* in_sizes, int n_in,
                              void* d_out, int out_size) {
    const float* x = (const float*)d_in[0];   // [S, D]
    const float* w = (const float*)d_in[1];   // [E, D]
    float* out = (float*)d_out;
    long long osz = (long long)out_size;

    k1_fused<<<GEMM_BLOCKS + TFB, 256>>>(x, w, out, osz);   // launch 0
    kT<<<137, 1024>>>(out);                                 // launch 1
}